// round 14
// baseline (speedup 1.0000x reference)
#include <cuda_runtime.h>
#include <math_constants.h>
#include <cstdint>

#define POOL 7
#define NUM_ROIS 300
#define HH 50
#define WW 50
#define CC 512
#define NPIX (HH * WW)
#define NBINS (POOL * POOL)
#define TOTAL_BINS (NUM_ROIS * NBINS)        // 14700
#define V4_PER_BIN (CC / 4)                  // 128 float4 per bin
#define WPB 8                                // warps per block
#define GRID2 ((TOTAL_BINS + WPB - 1) / WPB) // 1838

// Scratch: channel-max per pixel (10 KB). __device__ global (no allocation).
__device__ float g_fmax[NPIX];

// ---------------- K1: channel max per pixel (warp per pixel) ----------------
__global__ void fmax_kernel(const float* __restrict__ fm) {
    int gwarp = (blockIdx.x * blockDim.x + threadIdx.x) >> 5;
    int lane  = threadIdx.x & 31;
    if (gwarp < NPIX) {
        const float4* p = reinterpret_cast<const float4*>(fm + (size_t)gwarp * CC);
        float m = -CUDART_INF_F;
#pragma unroll
        for (int i = 0; i < 4; i++) {
            float4 v = p[lane + i * 32];
            m = fmaxf(m, fmaxf(fmaxf(v.x, v.y), fmaxf(v.z, v.w)));
        }
#pragma unroll
        for (int s = 16; s; s >>= 1)
            m = fmaxf(m, __shfl_xor_sync(0xffffffffu, m, s));
        if (lane == 0) g_fmax[gwarp] = m;
    }
    cudaTriggerProgrammaticLaunchCompletion();
}

// ---------------- K2: one warp per bin, divide-free predicated reduce ------
// Window is provably <= 8x8. Lane covers cells (r, c) and (r+4, c) of the
// fixed 8x8 grid with bounds predicates: no runtime divide on the load path.
__global__ void __launch_bounds__(WPB * 32) stream_warp_kernel(
    const float* __restrict__ rois, float* __restrict__ out) {
    int tid  = threadIdx.x;
    int lane = tid & 31;
    int g    = blockIdx.x * WPB + (tid >> 5);   // global bin id
    bool act = (g < TOTAL_BINS);
    int gc   = act ? g : 0;

    // ---- Prologue (overlaps K1 tail under PDL): window math from rois ----
    int roi = gc / NBINS;                       // const divisors -> mul/shift
    int bin = gc - roi * NBINS;
    int bi  = bin / POOL;
    int bj  = bin - bi * POOL;

    const float inv = 1.0f / 16.0f;
    int x1 = (int)(rois[roi * 5 + 1] * inv);
    int y1 = (int)(rois[roi * 5 + 2] * inv);
    int x2 = (int)(rois[roi * 5 + 3] * inv);
    int y2 = (int)(rois[roi * 5 + 4] * inv);
    int rh = y2 - y1 + 1;
    int rw = x2 - x1 + 1;

    int hs = min(max(y1 + (bi * rh) / POOL, 0), HH);
    int he = min(max(y1 + ((bi + 1) * rh + POOL - 1) / POOL, 0), HH);
    int ws = min(max(x1 + (bj * rw) / POOL, 0), WW);
    int we = min(max(x1 + ((bj + 1) * rw + POOL - 1) / POOL, 0), WW);

    int nh = he - hs;                           // <= 8
    int nw = we - ws;                           // <= 8

    // Fixed 8x8 enumeration: lane -> (r, c), covers rows r and r+4.
    int r = lane >> 3;                          // 0..3
    int c = lane & 7;                           // 0..7
    const float* base = g_fmax + hs * WW + ws;
    bool cok = (c < nw);
    bool p0  = cok & (r     < nh);
    bool p1  = cok & (r + 4 < nh);
    int  a0  = r * WW + c;
    int  a1  = a0 + 4 * WW;

    cudaGridDependencySynchronize();            // wait for g_fmax

    // ---- Reduce: 2 predicated hot loads + butterfly ----
    float m = -CUDART_INF_F;
    if (p0) m = base[a0];
    if (p1) m = fmaxf(m, base[a1]);
#pragma unroll
    for (int s = 16; s; s >>= 1)
        m = fmaxf(m, __shfl_xor_sync(0xffffffffu, m, s));
    // every lane now holds the bin max

    // ---- Stream this bin's 2KB: 4 independent streaming STG.128 per lane --
    if (act) {
        float4* o = reinterpret_cast<float4*>(out) + (size_t)g * V4_PER_BIN;
        float4 v4 = make_float4(m, m, m, m);
        __stcs(o + lane,      v4);
        __stcs(o + lane + 32, v4);
        __stcs(o + lane + 64, v4);
        __stcs(o + lane + 96, v4);
    }
}

extern "C" void kernel_launch(void* const* d_in, const int* in_sizes, int n_in,
                              void* d_out, int out_size) {
    const float* rois = (const float*)d_in[0];
    const float* fm   = (const float*)d_in[1];
    if (in_sizes[0] != NUM_ROIS * 5) {
        const float* t = rois; rois = fm; fm = t;
    }
    float* out = (float*)d_out;

    int threads1 = 256;
    int blocks1  = (NPIX * 32 + threads1 - 1) / threads1;
    fmax_kernel<<<blocks1, threads1>>>(fm);

    cudaLaunchAttribute attrs[1];
    attrs[0].id = cudaLaunchAttributeProgrammaticStreamSerialization;
    attrs[0].val.programmaticStreamSerializationAllowed = 1;

    cudaLaunchConfig_t cfg = {};
    cfg.gridDim  = dim3(GRID2, 1, 1);
    cfg.blockDim = dim3(WPB * 32, 1, 1);
    cfg.stream   = 0;
    cfg.attrs    = attrs;
    cfg.numAttrs = 1;

    cudaLaunchKernelEx(&cfg, stream_warp_kernel, rois, out);
}